// round 16
// baseline (speedup 1.0000x reference)
#include <cuda_runtime.h>
#include <cuda_fp16.h>
#include <cstdint>

#define D 128
#define NPAD 50048          // 391 * 128
#define NBLK 391
#define PA 68               // packed (fp16x2) row pitch in u32: 64 data + 4 pad
#define EMAX 1000000

// ---------------- device scratch ----------------
__device__ float g_S2[(size_t)NPAD * D];                      // x2 = x + perb (fp32)
__device__ __align__(16) uint32_t g_AggX[(size_t)NPAD * 64];  // Zx, packed half2
__device__ __align__(16) uint32_t g_AggZ2h[(size_t)NPAD * 64];// Z2 hi, packed half2
__device__ __align__(16) uint32_t g_AggZ2l[(size_t)NPAD * 64];// Z2 lo residual
__device__ __align__(16) uint32_t g_Hx[(size_t)NPAD * 64];    // packed half2
__device__ __align__(16) uint32_t g_Hy[(size_t)NPAD * 64];
__device__ float g_Wc[D * D];
__device__ float g_bc[D];
__device__ __align__(16) uint32_t g_Bh[4][D * PA];  // Wtg, Wc, Won, W2 (fp16 hi)
__device__ __align__(16) uint32_t g_Bl[4][D * PA];  // fp16 lo residual
__device__ float g_colsum[2][D];
__device__ float g_colsq[2][D];
__device__ double g_lossSum;
__device__ int   g_done;
// CSR (g_cur zero at load; every launch restores it to zero)
__device__ int   g_off[NPAD + 1];
__device__ int   g_cur[NPAD];
__device__ int   g_ecol2[EMAX];
__device__ float g_ew2[EMAX];

// ---------------- helpers ----------------
__device__ __forceinline__ uint32_t smem_u32(const void* p) {
    uint32_t a;
    asm("{ .reg .u64 t; cvta.to.shared.u64 t, %1; cvt.u32.u64 %0, t; }" : "=r"(a) : "l"(p));
    return a;
}
__device__ __forceinline__ void cpa16(uint32_t s, const void* g) {
    asm volatile("cp.async.ca.shared.global [%0], [%1], 16;" :: "r"(s), "l"(g));
}
#define CP_WAIT() \
    asm volatile("cp.async.commit_group;\n\tcp.async.wait_group 0;" ::: "memory")

__device__ __forceinline__ void hsplit(float x, float y, uint32_t& h, uint32_t& l) {
    __half2 hh = __floats2half2_rn(x, y);
    float2 hf = __half22float2(hh);
    __half2 ll = __floats2half2_rn(x - hf.x, y - hf.y);
    h = *reinterpret_cast<uint32_t*>(&hh);
    l = *reinterpret_cast<uint32_t*>(&ll);
}
__device__ __forceinline__ uint32_t hpack(float x, float y) {
    __half2 hh = __floats2half2_rn(x, y);
    return *reinterpret_cast<uint32_t*>(&hh);
}
__device__ __forceinline__ float2 hunpack(uint32_t v) {
    return __half22float2(*reinterpret_cast<__half2*>(&v));
}

// fp16 HMMA, fp32 accumulate (sm_80+ PTX)
#define MMA(cc, a, b0v, b1v) \
    asm("mma.sync.aligned.m16n8k16.row.col.f32.f16.f16.f32 " \
        "{%0,%1,%2,%3},{%4,%5,%6,%7},{%8,%9},{%0,%1,%2,%3};" \
        : "+f"((cc)[0]), "+f"((cc)[1]), "+f"((cc)[2]), "+f"((cc)[3]) \
        : "r"((a)[0]), "r"((a)[1]), "r"((a)[2]), "r"((a)[3]), \
          "r"(b0v), "r"(b1v))

#define LDSM4(r, addr) \
    asm volatile("ldmatrix.sync.aligned.m8n8.x4.shared.b16 {%0,%1,%2,%3}, [%4];" \
        : "=r"((r)[0]), "=r"((r)[1]), "=r"((r)[2]), "=r"((r)[3]) : "r"(addr))

// smem layout (u32 offsets): Ah, Al, single B, double bias, reduction, bn affine
#define SM_AH 0
#define SM_AL (D * PA)
#define SM_B  (2 * D * PA)
#define SM_BIAS (3 * D * PA)          // 2 x 128 floats
#define SM_RED (SM_BIAS + 256)        // psq/dot/tsq  3 x 128
#define SM_BN  (SM_RED + 384)         // bn scale[128], shift[128]
#define DYN_SMEM ((SM_BN + 256) * 4)  // 108032 B -> 2 CTAs/SM

// ---------------- fused: prep (x2 only) || count ----------------
__global__ void k_prep_count(const float* __restrict__ x, const float* __restrict__ perb,
                             const int* __restrict__ erow, int N, int E, int PREPB) {
    int b = blockIdx.x;
    int t = threadIdx.x;
    if (b < PREPB) {
        int idx = b * 256 + t;                 // float4 index into g_S2
        if (idx >= NPAD * 32) return;
        int n = idx >> 5, k = idx & 31;
        float4 v = make_float4(0.f, 0.f, 0.f, 0.f);
        if (n < N) {
            float4 a = ((const float4*)x)[(size_t)n * 32 + k];
            float4 p = ((const float4*)perb)[(size_t)n * 32 + k];
            v = make_float4(a.x + p.x, a.y + p.y, a.z + p.z, a.w + p.w);
        }
        ((float4*)g_S2)[idx] = v;
    } else {
        int e = (b - PREPB) * 256 + t;
        if (e < E) atomicAdd(&g_cur[__ldg(erow + e)], 1);
    }
}

// single-block exclusive scan over g_cur -> g_off; reset g_cur for scatter
__global__ void k_scan() {
    __shared__ int part[1024];
    const int CH = (NPAD + 1023) / 1024;   // 49
    int t = threadIdx.x;
    int base = t * CH;
    int s = 0;
    for (int i = 0; i < CH; i++) {
        int idx = base + i;
        if (idx < NPAD) s += g_cur[idx];
    }
    part[t] = s;
    __syncthreads();
    for (int off = 1; off < 1024; off <<= 1) {
        int u = (t >= off) ? part[t - off] : 0;
        __syncthreads();
        part[t] += u;
        __syncthreads();
    }
    int run = part[t] - s;
    for (int i = 0; i < CH; i++) {
        int idx = base + i;
        if (idx < NPAD) {
            g_off[idx] = run;
            run += g_cur[idx];
            g_cur[idx] = 0;
        }
    }
    if (t == 1023) g_off[NPAD] = part[1023];
}

// ---------------- fused: scatter || combine (Wc = Won@W1, bc = bon@W1+b1) ------
__global__ void k_scatter_combine(
    const int* __restrict__ erow, const int* __restrict__ ecol,
    const float* __restrict__ ew,
    const float* __restrict__ Won, const float* __restrict__ bon,
    const float* __restrict__ W1,  const float* __restrict__ b1,
    int E, int SCATB)
{
    int b = blockIdx.x;
    int t = threadIdx.x;
    if (b < SCATB) {
        int e = b * 256 + t;
        if (e >= E) return;
        int r = __ldg(erow + e);
        int pos = g_off[r] + atomicAdd(&g_cur[r], 1);
        g_ecol2[pos] = __ldg(ecol + e);
        g_ew2[pos]   = __ldg(ew + e);
    } else {
        __shared__ float row[D];
        int i = b - SCATB;           // 0..128
        int j = t;
        if (j < D) row[j] = (i < D) ? Won[i * D + j] : bon[j];
        __syncthreads();
        if (j < D) {
            float acc = (i < D) ? 0.f : b1[j];
            #pragma unroll 8
            for (int k = 0; k < D; k++) acc = fmaf(row[k], W1[k * D + j], acc);
            if (i < D) g_Wc[i * D + j] = acc;
            else       g_bc[j] = acc;
        }
    }
}

// ---------------- fused: wprep (16 blocks) || CSR aggregation ----------------
// lanes 0-15:  Zx = sum w*x[col]   -> g_AggX   (packed half2)
// lanes 16-31: Z2 = sum w*x2[col]  -> g_AggZ2h/g_AggZ2l (hi/lo packed half2)
__global__ __launch_bounds__(256) void k_agg_wprep(
    const float* __restrict__ x,
    const float* __restrict__ Wtg, const float* __restrict__ Won,
    const float* __restrict__ W2) {
    int b = blockIdx.x;
    int t = threadIdx.x;
    if (b < 16) {
        if (b == 0 && t >= 128) {
            int c = t - 128;
            g_colsum[0][c] = 0.f; g_colsum[1][c] = 0.f;
            g_colsq[0][c]  = 0.f; g_colsq[1][c]  = 0.f;
            if (c == 0) { g_lossSum = 0.0; g_done = 0; }
        }
        int w = b >> 2, quad = b & 3;
        if (t < 64) {
            const float* W = (w == 0) ? Wtg : (w == 1) ? g_Wc : (w == 2) ? Won : W2;
            int n = quad * 32 + (t >> 1), half = t & 1;
            #pragma unroll
            for (int j = 0; j < 32; j++) {
                int k = half * 64 + 2 * j;
                float v0 = W[(size_t)k * D + n];
                float v1 = W[(size_t)(k + 1) * D + n];
                uint32_t h, l;
                hsplit(v0, v1, h, l);
                g_Bh[w][n * PA + half * 32 + j] = h;
                g_Bl[w][n * PA + half * 32 + j] = l;
            }
        }
        return;
    }
    int wid = t >> 5, lane = t & 31;
    int n = (b - 16) * 8 + wid;
    int start = g_off[n];
    int deg = g_off[n + 1] - start;
    if (lane == 0) g_cur[n] = 0;          // restore invariant for next launch
    const float4* base = (lane < 16) ? (const float4*)x : (const float4*)g_S2;
    int loff = (lane & 15) * 2;
    float4 a0 = make_float4(0.f, 0.f, 0.f, 0.f), a1 = a0;
    for (int bb = 0; bb < deg; bb += 32) {
        int j = bb + lane;
        int cc = 0; float ww = 0.f;
        if (j < deg) { cc = g_ecol2[start + j]; ww = g_ew2[start + j]; }
        int cnt = min(32, deg - bb);
        int i = 0;
        for (; i + 4 <= cnt; i += 4) {
            int   c0 = __shfl_sync(0xffffffffu, cc, i);
            int   c1 = __shfl_sync(0xffffffffu, cc, i + 1);
            int   c2 = __shfl_sync(0xffffffffu, cc, i + 2);
            int   c3 = __shfl_sync(0xffffffffu, cc, i + 3);
            float w0 = __shfl_sync(0xffffffffu, ww, i);
            float w1 = __shfl_sync(0xffffffffu, ww, i + 1);
            float w2 = __shfl_sync(0xffffffffu, ww, i + 2);
            float w3 = __shfl_sync(0xffffffffu, ww, i + 3);
            const float4* p0 = base + (size_t)c0 * 32 + loff;
            const float4* p1 = base + (size_t)c1 * 32 + loff;
            const float4* p2 = base + (size_t)c2 * 32 + loff;
            const float4* p3 = base + (size_t)c3 * 32 + loff;
            float4 v00 = __ldg(p0), v01 = __ldg(p0 + 1);
            float4 v10 = __ldg(p1), v11 = __ldg(p1 + 1);
            float4 v20 = __ldg(p2), v21 = __ldg(p2 + 1);
            float4 v30 = __ldg(p3), v31 = __ldg(p3 + 1);
            a0.x = fmaf(w0, v00.x, a0.x); a0.y = fmaf(w0, v00.y, a0.y);
            a0.z = fmaf(w0, v00.z, a0.z); a0.w = fmaf(w0, v00.w, a0.w);
            a1.x = fmaf(w0, v01.x, a1.x); a1.y = fmaf(w0, v01.y, a1.y);
            a1.z = fmaf(w0, v01.z, a1.z); a1.w = fmaf(w0, v01.w, a1.w);
            a0.x = fmaf(w1, v10.x, a0.x); a0.y = fmaf(w1, v10.y, a0.y);
            a0.z = fmaf(w1, v10.z, a0.z); a0.w = fmaf(w1, v10.w, a0.w);
            a1.x = fmaf(w1, v11.x, a1.x); a1.y = fmaf(w1, v11.y, a1.y);
            a1.z = fmaf(w1, v11.z, a1.z); a1.w = fmaf(w1, v11.w, a1.w);
            a0.x = fmaf(w2, v20.x, a0.x); a0.y = fmaf(w2, v20.y, a0.y);
            a0.z = fmaf(w2, v20.z, a0.z); a0.w = fmaf(w2, v20.w, a0.w);
            a1.x = fmaf(w2, v21.x, a1.x); a1.y = fmaf(w2, v21.y, a1.y);
            a1.z = fmaf(w2, v21.z, a1.z); a1.w = fmaf(w2, v21.w, a1.w);
            a0.x = fmaf(w3, v30.x, a0.x); a0.y = fmaf(w3, v30.y, a0.y);
            a0.z = fmaf(w3, v30.z, a0.z); a0.w = fmaf(w3, v30.w, a0.w);
            a1.x = fmaf(w3, v31.x, a1.x); a1.y = fmaf(w3, v31.y, a1.y);
            a1.z = fmaf(w3, v31.z, a1.z); a1.w = fmaf(w3, v31.w, a1.w);
        }
        for (; i < cnt; i++) {
            int cs = __shfl_sync(0xffffffffu, cc, i);
            float ws = __shfl_sync(0xffffffffu, ww, i);
            const float4* src = base + (size_t)cs * 32 + loff;
            float4 v = __ldg(src);
            float4 u = __ldg(src + 1);
            a0.x = fmaf(ws, v.x, a0.x); a0.y = fmaf(ws, v.y, a0.y);
            a0.z = fmaf(ws, v.z, a0.z); a0.w = fmaf(ws, v.w, a0.w);
            a1.x = fmaf(ws, u.x, a1.x); a1.y = fmaf(ws, u.y, a1.y);
            a1.z = fmaf(ws, u.z, a1.z); a1.w = fmaf(ws, u.w, a1.w);
        }
    }
    if (lane < 16) {
        uint4 pk;
        pk.x = hpack(a0.x, a0.y);
        pk.y = hpack(a0.z, a0.w);
        pk.z = hpack(a1.x, a1.y);
        pk.w = hpack(a1.z, a1.w);
        *(uint4*)(g_AggX + (size_t)n * 64 + (lane & 15) * 4) = pk;
    } else {
        uint4 hi, lo;
        hsplit(a0.x, a0.y, hi.x, lo.x);
        hsplit(a0.z, a0.w, hi.y, lo.y);
        hsplit(a1.x, a1.y, hi.z, lo.z);
        hsplit(a1.z, a1.w, hi.w, lo.w);
        *(uint4*)(g_AggZ2h + (size_t)n * 64 + (lane & 15) * 4) = hi;
        *(uint4*)(g_AggZ2l + (size_t)n * 64 + (lane & 15) * 4) = lo;
    }
}

// ---------------- MMA pass via ldmatrix (A slot parameterized) ----------------
__device__ __forceinline__ void mma_pass(uint32_t sb, int wid, int lane,
                                         float c[4][4][4], bool dual, uint32_t aOff) {
    int warpM = wid & 1, warpN = wid >> 1;
    int arow = warpM * 64 + (lane & 15);
    uint32_t aA = sb + aOff * 4 + (uint32_t)(arow * PA + (lane >> 4) * 4) * 4;
    int brow = warpN * 32 + (lane & 7) + ((lane >> 4) & 1) * 8;
    uint32_t aB = sb + (uint32_t)(brow * PA + ((lane >> 3) & 1) * 4) * 4
                + (uint32_t)SM_B * 4;

    #pragma unroll
    for (int ks = 0; ks < 8; ks++) {
        uint32_t ah[4][4], b[2][4];
        #pragma unroll
        for (int mf = 0; mf < 4; mf++)
            LDSM4(ah[mf], aA + (uint32_t)(mf * 16 * PA) * 4 + ks * 32);
        #pragma unroll
        for (int p = 0; p < 2; p++)
            LDSM4(b[p], aB + (uint32_t)(p * 16 * PA) * 4 + ks * 32);
        #pragma unroll
        for (int mf = 0; mf < 4; mf++)
            #pragma unroll
            for (int p = 0; p < 2; p++) {
                MMA(c[mf][p * 2 + 0], ah[mf], b[p][0], b[p][1]);
                MMA(c[mf][p * 2 + 1], ah[mf], b[p][2], b[p][3]);
            }
        if (dual) {
            uint32_t al[4][4];
            #pragma unroll
            for (int mf = 0; mf < 4; mf++)
                LDSM4(al[mf], sb + (uint32_t)SM_AL * 4
                              + (uint32_t)(arow * PA + (lane >> 4) * 4) * 4
                              + (uint32_t)(mf * 16 * PA) * 4 + ks * 32);
            #pragma unroll
            for (int mf = 0; mf < 4; mf++)
                #pragma unroll
                for (int p = 0; p < 2; p++) {
                    MMA(c[mf][p * 2 + 0], al[mf], b[p][0], b[p][1]);
                    MMA(c[mf][p * 2 + 1], al[mf], b[p][2], b[p][3]);
                }
        }
    }
}

__device__ __forceinline__ void copyB(uint32_t sb, int tid, const uint32_t* src) {
    uint32_t bdst = sb + (uint32_t)SM_B * 4;
    const uint4* s4 = (const uint4*)src;
    for (int i = tid; i < D * PA / 4; i += 256) cpa16(bdst + i * 16, s4 + i);
}

// ---------------- stage-1 (Tgt removed — computed in pred) ----------------
// gy=0: A=Zx -> Hx (stats 0)
// gy=1: A=Z2 -> embed (3-term) -> dout, then Hy (stats 1)
__global__ __launch_bounds__(256, 2) void k_gemm_s1(
    const float* __restrict__ bon, float* __restrict__ dout, int N)
{
    extern __shared__ uint32_t sm[];
    float (*bias2)[128] = (float(*)[128])(sm + SM_BIAS);
    uint32_t sb = smem_u32(sm);

    int gy = blockIdx.y;
    int row0 = blockIdx.x * 128;
    int tid = threadIdx.x;
    int wid = tid >> 5, lane = tid & 31;
    int g = lane >> 2, tg = lane & 3;
    int warpM = wid & 1, warpN = wid >> 1;

    // async A copies (pre-packed/pre-split in global)
    {
        int m = tid >> 1, half = tid & 1;
        uint32_t dA = sb + (uint32_t)(SM_AH + m * PA + half * 32) * 4;
        if (gy) {
            const uint4* sh = (const uint4*)(g_AggZ2h + (size_t)(row0 + m) * 64 + half * 32);
            const uint4* sl = (const uint4*)(g_AggZ2l + (size_t)(row0 + m) * 64 + half * 32);
            uint32_t dL = sb + (uint32_t)(SM_AL + m * PA + half * 32) * 4;
            #pragma unroll
            for (int j = 0; j < 8; j++) {
                cpa16(dA + j * 16, sh + j);
                cpa16(dL + j * 16, sl + j);
            }
        } else {
            const uint4* sh = (const uint4*)(g_AggX + (size_t)(row0 + m) * 64 + half * 32);
            #pragma unroll
            for (int j = 0; j < 8; j++) cpa16(dA + j * 16, sh + j);
        }
    }
    copyB(sb, tid, gy ? g_Bh[2] : g_Bh[1]);  // gy1: Won, gy0: Wc
    if (tid < 128) bias2[0][tid] = gy ? bon[tid] : g_bc[tid];
    CP_WAIT();
    __syncthreads();

    int nsub = gy ? 2 : 1;
    for (int s = 0; s < nsub; s++) {
        int mode;                             // 1=H+stats, 2=embed
        uint32_t* outh = nullptr;
        int sidx = gy;
        if (gy == 0)     { mode = 1; outh = g_Hx; }
        else if (s == 0) { mode = 2; }
        else             { mode = 1; outh = g_Hy; }
        bool full = (mode == 2);

        float c[4][4][4];
        #pragma unroll
        for (int mf = 0; mf < 4; mf++)
            #pragma unroll
            for (int nf = 0; nf < 4; nf++)
                #pragma unroll
                for (int q = 0; q < 4; q++) c[mf][nf][q] = 0.f;

        mma_pass(sb, wid, lane, c, full, SM_AH);   // H: Ah@Bh; embed: (Ah+Al)@Bh
        if (full) {
            __syncthreads();
            copyB(sb, tid, g_Bl[2]);
            CP_WAIT();
            __syncthreads();
            mma_pass(sb, wid, lane, c, false, SM_AH);   // + Ah@Bl
        }

        __syncthreads();                      // all warps done reading B(s)
        if (s + 1 < nsub) {                   // prefetch Wc under epilogue
            copyB(sb, tid, g_Bh[1]);
            if (tid < 128) bias2[1][tid] = g_bc[tid];
        }
        const float* bias_s = bias2[s & 1];

        // epilogue
        float ls[8], lq[8];
        #pragma unroll
        for (int i = 0; i < 8; i++) { ls[i] = 0.f; lq[i] = 0.f; }

        #pragma unroll
        for (int mf = 0; mf < 4; mf++) {
            #pragma unroll
            for (int part = 0; part < 2; part++) {
                int n = row0 + warpM * 64 + mf * 16 + g + part * 8;
                #pragma unroll
                for (int nf = 0; nf < 4; nf++) {
                    int col = warpN * 32 + nf * 8 + 2 * tg;
                    float v0 = c[mf][nf][part * 2]     + bias_s[col];
                    float v1 = c[mf][nf][part * 2 + 1] + bias_s[col + 1];
                    if (mode == 2) {
                        if (n < N) {
                            float2 s2 = *(const float2*)(g_S2 + (size_t)n * D + col);
                            *(float2*)(dout + (size_t)n * D + col) =
                                make_float2(v0 + s2.x, v1 + s2.y);
                        }
                    } else {
                        outh[(size_t)n * 64 + (col >> 1)] = hpack(v0, v1);
                        if (n < N) {
                            ls[nf * 2]     += v0; lq[nf * 2]     += v0 * v0;
                            ls[nf * 2 + 1] += v1; lq[nf * 2 + 1] += v1 * v1;
                        }
                    }
                }
            }
        }
        if (mode == 1) {
            #pragma unroll
            for (int i = 0; i < 8; i++) {
                #pragma unroll
                for (int off = 4; off < 32; off <<= 1) {
                    ls[i] += __shfl_xor_sync(0xffffffffu, ls[i], off);
                    lq[i] += __shfl_xor_sync(0xffffffffu, lq[i], off);
                }
            }
            if (g == 0) {
                #pragma unroll
                for (int nf = 0; nf < 4; nf++) {
                    #pragma unroll
                    for (int j = 0; j < 2; j++) {
                        int col = warpN * 32 + nf * 8 + 2 * tg + j;
                        atomicAdd(&g_colsum[sidx][col], ls[nf * 2 + j]);
                        atomicAdd(&g_colsq[sidx][col],  lq[nf * 2 + j]);
                    }
                }
            }
        }
        if (s + 1 < nsub) {
            CP_WAIT();
            __syncthreads();
        }
    }
}

// ---------------- stage-2: T = Z@Wtg+btg (in-kernel), P = BN(H)@W2+b2, loss ----
// tag0: H=Hx, Z=Z2h;  tag1: H=Hy, Z=Zx.  T staged in SM_AL (half2), never global.
__global__ __launch_bounds__(256, 2) void k_pred_s2(
    const float* __restrict__ bng, const float* __restrict__ bnb,
    const float* __restrict__ btg, const float* __restrict__ b2,
    const float* __restrict__ prelu_a, float* __restrict__ dout, int N)
{
    extern __shared__ uint32_t sm[];
    float (*bias2)[128] = (float(*)[128])(sm + SM_BIAS);   // [0]=b2, [1]=btg
    float* sred = (float*)(sm + SM_RED);
    float* bnsc = (float*)(sm + SM_BN);
    float* bnsh = bnsc + 128;
    uint32_t sb = smem_u32(sm);

    int tag = blockIdx.y;
    int row0 = blockIdx.x * 128;
    int tid = threadIdx.x;
    int wid = tid >> 5, lane = tid & 31;
    int g = lane >> 2, tg = lane & 3;
    int warpM = wid & 1, warpN = wid >> 1;
    const uint32_t* H = tag ? g_Hy : g_Hx;
    const uint32_t* Z = tag ? g_AggX : g_AggZ2h;
    float slope = prelu_a[0];

    // async: A2 (Z) -> SM_AL, Wtg -> SM_B
    {
        int m = tid >> 1, half = tid & 1;
        uint32_t dL = sb + (uint32_t)(SM_AL + m * PA + half * 32) * 4;
        const uint4* sz = (const uint4*)(Z + (size_t)(row0 + m) * 64 + half * 32);
        #pragma unroll
        for (int j = 0; j < 8; j++) cpa16(dL + j * 16, sz + j);
    }
    copyB(sb, tid, g_Bh[0]);                  // Wtg
    if (tid < 128) {
        float inv = 1.f / (float)N;
        float mu  = g_colsum[tag][tid] * inv;
        float var = g_colsq[tag][tid] * inv - mu * mu;
        float istd = rsqrtf(var + 1e-5f);
        float sc = bng[tid] * istd;
        bnsc[tid] = sc;
        bnsh[tid] = bnb[tid] - mu * sc;
        bias2[0][tid] = b2[tid];
        bias2[1][tid] = btg[tid];
        sred[tid] = 0.f; sred[128 + tid] = 0.f; sred[256 + tid] = 0.f;
    }
    __syncthreads();                          // bn affine visible

    // fill AH = PReLU(BN(H)) from packed-half2 H
    {
        int m = tid >> 1, half = tid & 1;
        const uint4* hrow = (const uint4*)(H + (size_t)(row0 + m) * 64 + half * 32);
        const float2* scp = (const float2*)bnsc + half * 32;
        const float2* shp = (const float2*)bnsh + half * 32;
        uint32_t* dH = sm + SM_AH + m * PA + half * 32;
        #pragma unroll
        for (int j = 0; j < 8; j++) {
            uint4 hv = hrow[j];
            uint32_t comps[4] = {hv.x, hv.y, hv.z, hv.w};
            #pragma unroll
            for (int q = 0; q < 4; q++) {
                float2 f  = hunpack(comps[q]);
                float2 sc = scp[j * 4 + q];
                float2 sh = shp[j * 4 + q];
                float a0 = fmaf(f.x, sc.x, sh.x);
                float a1 = fmaf(f.y, sc.y, sh.y);
                a0 = a0 > 0.f ? a0 : slope * a0;
                a1 = a1 > 0.f ? a1 : slope * a1;
                dH[j * 4 + q] = hpack(a0, a1);
            }
        }
    }
    CP_WAIT();
    __syncthreads();

    float c[4][4][4];
    #pragma unroll
    for (int mf = 0; mf < 4; mf++)
        #pragma unroll
        for (int nf = 0; nf < 4; nf++)
            #pragma unroll
            for (int q = 0; q < 4; q++) c[mf][nf][q] = 0.f;

    mma_pass(sb, wid, lane, c, false, SM_AL);   // T = Z @ Wtg (1-term)
    __syncthreads();                             // all warps done reading A2
    copyB(sb, tid, g_Bh[3]);                     // prefetch W2 under staging

    // stage T+btg into SM_AL as half2 (bank = 4g+tg = conflict-free)
    #pragma unroll
    for (int mf = 0; mf < 4; mf++) {
        #pragma unroll
        for (int part = 0; part < 2; part++) {
            int r = warpM * 64 + mf * 16 + g + part * 8;
            #pragma unroll
            for (int nf = 0; nf < 4; nf++) {
                int col = warpN * 32 + nf * 8 + 2 * tg;
                sm[SM_AL + r * PA + (col >> 1)] =
                    hpack(c[mf][nf][part * 2]     + bias2[1][col],
                          c[mf][nf][part * 2 + 1] + bias2[1][col + 1]);
            }
        }
    }
    CP_WAIT();
    __syncthreads();

    #pragma unroll
    for (int mf = 0; mf < 4; mf++)
        #pragma unroll
        for (int nf = 0; nf < 4; nf++)
            #pragma unroll
            for (int q = 0; q < 4; q++) c[mf][nf][q] = 0.f;

    mma_pass(sb, wid, lane, c, false, SM_AH);   // P = BN(H) @ W2 (1-term)

    #pragma unroll
    for (int mf = 0; mf < 4; mf++) {
        #pragma unroll
        for (int part = 0; part < 2; part++) {
            int r = warpM * 64 + mf * 16 + g + part * 8;
            float psq = 0.f, dot = 0.f, tsq = 0.f;
            #pragma unroll
            for (int nf = 0; nf < 4; nf++) {
                int col = warpN * 32 + nf * 8 + 2 * tg;
                float v0 = c[mf][nf][part * 2]     + bias2[0][col];
                float v1 = c[mf][nf][part * 2 + 1] + bias2[0][col + 1];
                float2 t2 = hunpack(sm[SM_AL + r * PA + (col >> 1)]);
                psq = fmaf(v0, v0, fmaf(v1, v1, psq));
                dot = fmaf(v0, t2.x, fmaf(v1, t2.y, dot));
                tsq = fmaf(t2.x, t2.x, fmaf(t2.y, t2.y, tsq));
            }
            atomicAdd(&sred[r], psq);
            atomicAdd(&sred[128 + r], dot);
            atomicAdd(&sred[256 + r], tsq);
        }
    }
    __syncthreads();

    if (tid < 128) {
        int n = row0 + tid;
        float lossv = 0.f;
        if (n < N) {
            float denom = fmaxf(sqrtf(sred[tid]), 1e-12f) *
                          fmaxf(sqrtf(sred[256 + tid]), 1e-12f);
            lossv = 2.f - 2.f * sred[128 + tid] / denom;
        }
        #pragma unroll
        for (int o = 16; o; o >>= 1) lossv += __shfl_xor_sync(0xffffffffu, lossv, o);
        if (lane == 0) atomicAdd(&g_lossSum, (double)lossv);
    }
    __syncthreads();
    if (tid == 0) {
        __threadfence();
        int d = atomicAdd(&g_done, 1);
        if (d == 2 * NBLK - 1) {
            dout[(size_t)N * D] = (float)(g_lossSum / (double)N);
            g_done = 0;                       // restore invariant
        }
    }
}

// ---------------- launch ----------------
extern "C" void kernel_launch(void* const* d_in, const int* in_sizes, int n_in,
                              void* d_out, int out_size) {
    const float* x    = (const float*)d_in[0];
    const float* perb = (const float*)d_in[1];
    const int*   erow = (const int*)d_in[2];
    const int*   ecol = (const int*)d_in[3];
    const float* ew   = (const float*)d_in[4];
    const float* Won  = (const float*)d_in[5];
    const float* bon  = (const float*)d_in[6];
    const float* Wtg  = (const float*)d_in[7];
    const float* btg  = (const float*)d_in[8];
    const float* W1   = (const float*)d_in[9];
    const float* b1   = (const float*)d_in[10];
    const float* bng  = (const float*)d_in[11];
    const float* bnb  = (const float*)d_in[12];
    const float* pa   = (const float*)d_in[13];
    const float* W2   = (const float*)d_in[14];
    const float* b2   = (const float*)d_in[15];
    float* out = (float*)d_out;

    int N = in_sizes[0] / D;
    int E = in_sizes[2];
    if (N > NPAD) N = NPAD;
    if (E > EMAX) E = EMAX;

    cudaFuncSetAttribute(k_gemm_s1, cudaFuncAttributeMaxDynamicSharedMemorySize, DYN_SMEM);
    cudaFuncSetAttribute(k_pred_s2, cudaFuncAttributeMaxDynamicSharedMemorySize, DYN_SMEM);

    const int PREPB = NPAD * 32 / 256;       // 6256
    int EB = (E + 255) / 256;

    k_prep_count<<<PREPB + EB, 256>>>(x, perb, erow, N, E, PREPB);
    k_scan<<<1, 1024>>>();
    k_scatter_combine<<<EB + D + 1, 256>>>(erow, ecol, ew, Won, bon, W1, b1, E, EB);
    k_agg_wprep<<<16 + NPAD / 8, 256>>>(x, Wtg, Won, W2);
    dim3 g1(NBLK, 2);
    k_gemm_s1<<<g1, 256, DYN_SMEM>>>(bon, out, N);
    dim3 g2(NBLK, 2);
    k_pred_s2<<<g2, 256, DYN_SMEM>>>(bng, bnb, btg, b2, pa, out, N);
}

// round 17
// speedup vs baseline: 1.5107x; 1.5107x over previous
#include <cuda_runtime.h>
#include <cuda_fp16.h>
#include <cstdint>

#define D 128
#define NPAD 50048          // 391 * 128
#define NBLK 391
#define PA 68               // packed (fp16x2) row pitch in u32: 64 data + 4 pad
#define EMAX 1000000

// ---------------- device scratch ----------------
__device__ float g_S2[(size_t)NPAD * D];                      // x2 = x + perb (fp32)
__device__ __align__(16) uint32_t g_AggX[(size_t)NPAD * 64];  // Zx, packed half2
__device__ __align__(16) uint32_t g_AggZ2h[(size_t)NPAD * 64];// Z2 hi, packed half2
__device__ __align__(16) uint32_t g_AggZ2l[(size_t)NPAD * 64];// Z2 lo residual
__device__ __align__(16) uint32_t g_TgtX[(size_t)NPAD * 64];  // packed half2
__device__ __align__(16) uint32_t g_TgtY[(size_t)NPAD * 64];
__device__ __align__(16) uint32_t g_Hx[(size_t)NPAD * 64];
__device__ __align__(16) uint32_t g_Hy[(size_t)NPAD * 64];
__device__ float g_Wc[D * D];
__device__ float g_bc[D];
__device__ __align__(16) uint32_t g_Bh[4][D * PA];  // Wtg, Wc, Won, W2 (fp16 hi)
__device__ __align__(16) uint32_t g_Bl[4][D * PA];  // fp16 lo residual
__device__ float g_colsum[2][D];
__device__ float g_colsq[2][D];
__device__ double g_lossSum;
// CSR (g_cur zero at load; every launch restores it to zero)
__device__ int   g_off[NPAD + 1];
__device__ int   g_cur[NPAD];
__device__ int   g_ecol2[EMAX];
__device__ float g_ew2[EMAX];

// ---------------- helpers ----------------
__device__ __forceinline__ uint32_t smem_u32(const void* p) {
    uint32_t a;
    asm("{ .reg .u64 t; cvta.to.shared.u64 t, %1; cvt.u32.u64 %0, t; }" : "=r"(a) : "l"(p));
    return a;
}
__device__ __forceinline__ void cpa16(uint32_t s, const void* g) {
    asm volatile("cp.async.ca.shared.global [%0], [%1], 16;" :: "r"(s), "l"(g));
}
#define CP_WAIT() \
    asm volatile("cp.async.commit_group;\n\tcp.async.wait_group 0;" ::: "memory")

__device__ __forceinline__ void hsplit(float x, float y, uint32_t& h, uint32_t& l) {
    __half2 hh = __floats2half2_rn(x, y);
    float2 hf = __half22float2(hh);
    __half2 ll = __floats2half2_rn(x - hf.x, y - hf.y);
    h = *reinterpret_cast<uint32_t*>(&hh);
    l = *reinterpret_cast<uint32_t*>(&ll);
}
__device__ __forceinline__ uint32_t hpack(float x, float y) {
    __half2 hh = __floats2half2_rn(x, y);
    return *reinterpret_cast<uint32_t*>(&hh);
}
__device__ __forceinline__ float2 hunpack(uint32_t v) {
    return __half22float2(*reinterpret_cast<__half2*>(&v));
}

// fp16 HMMA, fp32 accumulate (sm_80+ PTX)
#define MMA(cc, a, b0v, b1v) \
    asm("mma.sync.aligned.m16n8k16.row.col.f32.f16.f16.f32 " \
        "{%0,%1,%2,%3},{%4,%5,%6,%7},{%8,%9},{%0,%1,%2,%3};" \
        : "+f"((cc)[0]), "+f"((cc)[1]), "+f"((cc)[2]), "+f"((cc)[3]) \
        : "r"((a)[0]), "r"((a)[1]), "r"((a)[2]), "r"((a)[3]), \
          "r"(b0v), "r"(b1v))

#define LDSM4(r, addr) \
    asm volatile("ldmatrix.sync.aligned.m8n8.x4.shared.b16 {%0,%1,%2,%3}, [%4];" \
        : "=r"((r)[0]), "=r"((r)[1]), "=r"((r)[2]), "=r"((r)[3]) : "r"(addr))

// smem layout (u32 offsets): Ah, Al, single B, double bias, reduction, bn affine
#define SM_AH 0
#define SM_AL (D * PA)
#define SM_B  (2 * D * PA)
#define SM_BIAS (3 * D * PA)          // 2 x 128 floats (double-buffered)
#define SM_RED (SM_BIAS + 256)        // psq/dot/tsq  3 x 128
#define SM_BN  (SM_RED + 384)         // bn scale[128], shift[128]
#define DYN_SMEM ((SM_BN + 256) * 4)  // 108032 B -> 2 CTAs/SM

// ---------------- fused: prep (x2 only) || count ----------------
__global__ void k_prep_count(const float* __restrict__ x, const float* __restrict__ perb,
                             const int* __restrict__ erow, int N, int E, int PREPB) {
    int b = blockIdx.x;
    int t = threadIdx.x;
    if (b < PREPB) {
        int idx = b * 256 + t;                 // float4 index into g_S2
        if (idx >= NPAD * 32) return;
        int n = idx >> 5, k = idx & 31;
        float4 v = make_float4(0.f, 0.f, 0.f, 0.f);
        if (n < N) {
            float4 a = ((const float4*)x)[(size_t)n * 32 + k];
            float4 p = ((const float4*)perb)[(size_t)n * 32 + k];
            v = make_float4(a.x + p.x, a.y + p.y, a.z + p.z, a.w + p.w);
        }
        ((float4*)g_S2)[idx] = v;
    } else {
        int e = (b - PREPB) * 256 + t;
        if (e < E) atomicAdd(&g_cur[__ldg(erow + e)], 1);
    }
}

// single-block exclusive scan over g_cur -> g_off; reset g_cur for scatter
__global__ void k_scan() {
    __shared__ int part[1024];
    const int CH = (NPAD + 1023) / 1024;   // 49
    int t = threadIdx.x;
    int base = t * CH;
    int s = 0;
    for (int i = 0; i < CH; i++) {
        int idx = base + i;
        if (idx < NPAD) s += g_cur[idx];
    }
    part[t] = s;
    __syncthreads();
    for (int off = 1; off < 1024; off <<= 1) {
        int u = (t >= off) ? part[t - off] : 0;
        __syncthreads();
        part[t] += u;
        __syncthreads();
    }
    int run = part[t] - s;
    for (int i = 0; i < CH; i++) {
        int idx = base + i;
        if (idx < NPAD) {
            g_off[idx] = run;
            run += g_cur[idx];
            g_cur[idx] = 0;
        }
    }
    if (t == 1023) g_off[NPAD] = part[1023];
}

// ---------------- fused: scatter || combine (Wc = Won@W1, bc = bon@W1+b1) ------
__global__ void k_scatter_combine(
    const int* __restrict__ erow, const int* __restrict__ ecol,
    const float* __restrict__ ew,
    const float* __restrict__ Won, const float* __restrict__ bon,
    const float* __restrict__ W1,  const float* __restrict__ b1,
    int E, int SCATB)
{
    int b = blockIdx.x;
    int t = threadIdx.x;
    if (b < SCATB) {
        int e = b * 256 + t;
        if (e >= E) return;
        int r = __ldg(erow + e);
        int pos = g_off[r] + atomicAdd(&g_cur[r], 1);
        g_ecol2[pos] = __ldg(ecol + e);
        g_ew2[pos]   = __ldg(ew + e);
    } else {
        __shared__ float row[D];
        int i = b - SCATB;           // 0..128
        int j = t;
        if (j < D) row[j] = (i < D) ? Won[i * D + j] : bon[j];
        __syncthreads();
        if (j < D) {
            float acc = (i < D) ? 0.f : b1[j];
            #pragma unroll 8
            for (int k = 0; k < D; k++) acc = fmaf(row[k], W1[k * D + j], acc);
            if (i < D) g_Wc[i * D + j] = acc;
            else       g_bc[j] = acc;
        }
    }
}

// ---------------- fused: wprep (16 blocks) || CSR aggregation ----------------
// lanes 0-15:  Zx = sum w*x[col]   -> g_AggX   (packed half2)
// lanes 16-31: Z2 = sum w*x2[col]  -> g_AggZ2h/g_AggZ2l (hi/lo packed half2)
__global__ __launch_bounds__(256) void k_agg_wprep(
    const float* __restrict__ x,
    const float* __restrict__ Wtg, const float* __restrict__ Won,
    const float* __restrict__ W2) {
    int b = blockIdx.x;
    int t = threadIdx.x;
    if (b < 16) {
        if (b == 0 && t >= 128) {
            int c = t - 128;
            g_colsum[0][c] = 0.f; g_colsum[1][c] = 0.f;
            g_colsq[0][c]  = 0.f; g_colsq[1][c]  = 0.f;
            if (c == 0) g_lossSum = 0.0;
        }
        int w = b >> 2, quad = b & 3;
        if (t < 64) {
            const float* W = (w == 0) ? Wtg : (w == 1) ? g_Wc : (w == 2) ? Won : W2;
            int n = quad * 32 + (t >> 1), half = t & 1;
            #pragma unroll
            for (int j = 0; j < 32; j++) {
                int k = half * 64 + 2 * j;
                float v0 = W[(size_t)k * D + n];
                float v1 = W[(size_t)(k + 1) * D + n];
                uint32_t h, l;
                hsplit(v0, v1, h, l);
                g_Bh[w][n * PA + half * 32 + j] = h;
                g_Bl[w][n * PA + half * 32 + j] = l;
            }
        }
        return;
    }
    int wid = t >> 5, lane = t & 31;
    int n = (b - 16) * 8 + wid;
    int start = g_off[n];
    int deg = g_off[n + 1] - start;
    if (lane == 0) g_cur[n] = 0;          // restore invariant for next launch
    const float4* base = (lane < 16) ? (const float4*)x : (const float4*)g_S2;
    int loff = (lane & 15) * 2;
    float4 a0 = make_float4(0.f, 0.f, 0.f, 0.f), a1 = a0;
    for (int bb = 0; bb < deg; bb += 32) {
        int j = bb + lane;
        int cc = 0; float ww = 0.f;
        if (j < deg) { cc = g_ecol2[start + j]; ww = g_ew2[start + j]; }
        int cnt = min(32, deg - bb);
        int i = 0;
        for (; i + 4 <= cnt; i += 4) {
            int   c0 = __shfl_sync(0xffffffffu, cc, i);
            int   c1 = __shfl_sync(0xffffffffu, cc, i + 1);
            int   c2 = __shfl_sync(0xffffffffu, cc, i + 2);
            int   c3 = __shfl_sync(0xffffffffu, cc, i + 3);
            float w0 = __shfl_sync(0xffffffffu, ww, i);
            float w1 = __shfl_sync(0xffffffffu, ww, i + 1);
            float w2 = __shfl_sync(0xffffffffu, ww, i + 2);
            float w3 = __shfl_sync(0xffffffffu, ww, i + 3);
            const float4* p0 = base + (size_t)c0 * 32 + loff;
            const float4* p1 = base + (size_t)c1 * 32 + loff;
            const float4* p2 = base + (size_t)c2 * 32 + loff;
            const float4* p3 = base + (size_t)c3 * 32 + loff;
            float4 v00 = __ldg(p0), v01 = __ldg(p0 + 1);
            float4 v10 = __ldg(p1), v11 = __ldg(p1 + 1);
            float4 v20 = __ldg(p2), v21 = __ldg(p2 + 1);
            float4 v30 = __ldg(p3), v31 = __ldg(p3 + 1);
            a0.x = fmaf(w0, v00.x, a0.x); a0.y = fmaf(w0, v00.y, a0.y);
            a0.z = fmaf(w0, v00.z, a0.z); a0.w = fmaf(w0, v00.w, a0.w);
            a1.x = fmaf(w0, v01.x, a1.x); a1.y = fmaf(w0, v01.y, a1.y);
            a1.z = fmaf(w0, v01.z, a1.z); a1.w = fmaf(w0, v01.w, a1.w);
            a0.x = fmaf(w1, v10.x, a0.x); a0.y = fmaf(w1, v10.y, a0.y);
            a0.z = fmaf(w1, v10.z, a0.z); a0.w = fmaf(w1, v10.w, a0.w);
            a1.x = fmaf(w1, v11.x, a1.x); a1.y = fmaf(w1, v11.y, a1.y);
            a1.z = fmaf(w1, v11.z, a1.z); a1.w = fmaf(w1, v11.w, a1.w);
            a0.x = fmaf(w2, v20.x, a0.x); a0.y = fmaf(w2, v20.y, a0.y);
            a0.z = fmaf(w2, v20.z, a0.z); a0.w = fmaf(w2, v20.w, a0.w);
            a1.x = fmaf(w2, v21.x, a1.x); a1.y = fmaf(w2, v21.y, a1.y);
            a1.z = fmaf(w2, v21.z, a1.z); a1.w = fmaf(w2, v21.w, a1.w);
            a0.x = fmaf(w3, v30.x, a0.x); a0.y = fmaf(w3, v30.y, a0.y);
            a0.z = fmaf(w3, v30.z, a0.z); a0.w = fmaf(w3, v30.w, a0.w);
            a1.x = fmaf(w3, v31.x, a1.x); a1.y = fmaf(w3, v31.y, a1.y);
            a1.z = fmaf(w3, v31.z, a1.z); a1.w = fmaf(w3, v31.w, a1.w);
        }
        for (; i < cnt; i++) {
            int cs = __shfl_sync(0xffffffffu, cc, i);
            float ws = __shfl_sync(0xffffffffu, ww, i);
            const float4* src = base + (size_t)cs * 32 + loff;
            float4 v = __ldg(src);
            float4 u = __ldg(src + 1);
            a0.x = fmaf(ws, v.x, a0.x); a0.y = fmaf(ws, v.y, a0.y);
            a0.z = fmaf(ws, v.z, a0.z); a0.w = fmaf(ws, v.w, a0.w);
            a1.x = fmaf(ws, u.x, a1.x); a1.y = fmaf(ws, u.y, a1.y);
            a1.z = fmaf(ws, u.z, a1.z); a1.w = fmaf(ws, u.w, a1.w);
        }
    }
    if (lane < 16) {
        uint4 pk;
        pk.x = hpack(a0.x, a0.y);
        pk.y = hpack(a0.z, a0.w);
        pk.z = hpack(a1.x, a1.y);
        pk.w = hpack(a1.z, a1.w);
        *(uint4*)(g_AggX + (size_t)n * 64 + (lane & 15) * 4) = pk;
    } else {
        uint4 hi, lo;
        hsplit(a0.x, a0.y, hi.x, lo.x);
        hsplit(a0.z, a0.w, hi.y, lo.y);
        hsplit(a1.x, a1.y, hi.z, lo.z);
        hsplit(a1.z, a1.w, hi.w, lo.w);
        *(uint4*)(g_AggZ2h + (size_t)n * 64 + (lane & 15) * 4) = hi;
        *(uint4*)(g_AggZ2l + (size_t)n * 64 + (lane & 15) * 4) = lo;
    }
}

// ---------------- MMA pass via ldmatrix ----------------
__device__ __forceinline__ void mma_pass(uint32_t sb, int wid, int lane,
                                         float c[4][4][4], bool dual) {
    int warpM = wid & 1, warpN = wid >> 1;
    int arow = warpM * 64 + (lane & 15);
    uint32_t aA = sb + (uint32_t)(arow * PA + (lane >> 4) * 4) * 4;
    int brow = warpN * 32 + (lane & 7) + ((lane >> 4) & 1) * 8;
    uint32_t aB = sb + (uint32_t)(brow * PA + ((lane >> 3) & 1) * 4) * 4
                + (uint32_t)SM_B * 4;

    #pragma unroll
    for (int ks = 0; ks < 8; ks++) {
        uint32_t ah[4][4], b[2][4];
        #pragma unroll
        for (int mf = 0; mf < 4; mf++)
            LDSM4(ah[mf], aA + (uint32_t)(mf * 16 * PA) * 4 + ks * 32);
        #pragma unroll
        for (int p = 0; p < 2; p++)
            LDSM4(b[p], aB + (uint32_t)(p * 16 * PA) * 4 + ks * 32);
        #pragma unroll
        for (int mf = 0; mf < 4; mf++)
            #pragma unroll
            for (int p = 0; p < 2; p++) {
                MMA(c[mf][p * 2 + 0], ah[mf], b[p][0], b[p][1]);
                MMA(c[mf][p * 2 + 1], ah[mf], b[p][2], b[p][3]);
            }
        if (dual) {
            uint32_t al[4][4];
            #pragma unroll
            for (int mf = 0; mf < 4; mf++)
                LDSM4(al[mf], aA + (uint32_t)SM_AL * 4
                              + (uint32_t)(mf * 16 * PA) * 4 + ks * 32);
            #pragma unroll
            for (int mf = 0; mf < 4; mf++)
                #pragma unroll
                for (int p = 0; p < 2; p++) {
                    MMA(c[mf][p * 2 + 0], al[mf], b[p][0], b[p][1]);
                    MMA(c[mf][p * 2 + 1], al[mf], b[p][2], b[p][3]);
                }
        }
    }
}

__device__ __forceinline__ void copyB(uint32_t sb, int tid, const uint32_t* src) {
    uint32_t bdst = sb + (uint32_t)SM_B * 4;
    const uint4* s4 = (const uint4*)src;
    for (int i = tid; i < D * PA / 4; i += 256) cpa16(bdst + i * 16, s4 + i);
}

// ---------------- stage-1 ----------------
// gy=0: A=Zx (pre-packed fp16)  -> TgtY (s0), Hx (s1, stats 0)
// gy=1: A=Z2 (pre-split hi/lo)  -> TgtX (s0), Hy (s1, stats 1), embed (s2) -> dout
__global__ __launch_bounds__(256, 2) void k_gemm_s1(
    const float* __restrict__ bon, const float* __restrict__ btg,
    float* __restrict__ dout, int N)
{
    extern __shared__ uint32_t sm[];
    float (*bias2)[128] = (float(*)[128])(sm + SM_BIAS);
    uint32_t sb = smem_u32(sm);

    int gy = blockIdx.y;
    int row0 = blockIdx.x * 128;
    int tid = threadIdx.x;
    int wid = tid >> 5, lane = tid & 31;
    int g = lane >> 2, tg = lane & 3;
    int warpM = wid & 1, warpN = wid >> 1;

    // async A copies (pre-packed/pre-split in global)
    {
        int m = tid >> 1, half = tid & 1;
        uint32_t dA = sb + (uint32_t)(SM_AH + m * PA + half * 32) * 4;
        if (gy) {
            const uint4* sh = (const uint4*)(g_AggZ2h + (size_t)(row0 + m) * 64 + half * 32);
            const uint4* sl = (const uint4*)(g_AggZ2l + (size_t)(row0 + m) * 64 + half * 32);
            uint32_t dL = sb + (uint32_t)(SM_AL + m * PA + half * 32) * 4;
            #pragma unroll
            for (int j = 0; j < 8; j++) {
                cpa16(dA + j * 16, sh + j);
                cpa16(dL + j * 16, sl + j);
            }
        } else {
            const uint4* sh = (const uint4*)(g_AggX + (size_t)(row0 + m) * 64 + half * 32);
            #pragma unroll
            for (int j = 0; j < 8; j++) cpa16(dA + j * 16, sh + j);
        }
    }
    copyB(sb, tid, g_Bh[0]);                 // first B = Wtg
    if (tid < 128) bias2[0][tid] = btg[tid];
    CP_WAIT();
    __syncthreads();

    int nsub = gy ? 3 : 2;
    for (int s = 0; s < nsub; s++) {
        int mode;                             // 0=Tgt, 1=H+stats, 2=embed
        uint32_t* outh = nullptr;
        int sidx = gy;
        if (s == 0)      { outh = gy ? g_TgtX : g_TgtY; mode = 0; }
        else if (s == 1) { outh = gy ? g_Hy   : g_Hx;   mode = 1; }
        else             { mode = 2; }
        bool full = (mode == 2);

        float c[4][4][4];
        #pragma unroll
        for (int mf = 0; mf < 4; mf++)
            #pragma unroll
            for (int nf = 0; nf < 4; nf++)
                #pragma unroll
                for (int q = 0; q < 4; q++) c[mf][nf][q] = 0.f;

        mma_pass(sb, wid, lane, c, full);     // loss: Ah@Bh; embed: (Ah+Al)@Bh
        if (full) {
            __syncthreads();
            copyB(sb, tid, g_Bl[2]);
            CP_WAIT();
            __syncthreads();
            mma_pass(sb, wid, lane, c, false);   // + Ah@Bl
        }

        __syncthreads();                      // all warps done reading B(s)
        if (s + 1 < nsub) {                   // prefetch next B under epilogue
            copyB(sb, tid, g_Bh[s + 1]);
            if (tid < 128)
                bias2[(s + 1) & 1][tid] = (s + 1 == 1) ? g_bc[tid] : bon[tid];
        }
        const float* bias_s = bias2[s & 1];

        // epilogue
        float ls[8], lq[8];
        #pragma unroll
        for (int i = 0; i < 8; i++) { ls[i] = 0.f; lq[i] = 0.f; }

        #pragma unroll
        for (int mf = 0; mf < 4; mf++) {
            #pragma unroll
            for (int part = 0; part < 2; part++) {
                int n = row0 + warpM * 64 + mf * 16 + g + part * 8;
                #pragma unroll
                for (int nf = 0; nf < 4; nf++) {
                    int col = warpN * 32 + nf * 8 + 2 * tg;
                    float v0 = c[mf][nf][part * 2]     + bias_s[col];
                    float v1 = c[mf][nf][part * 2 + 1] + bias_s[col + 1];
                    if (mode == 2) {
                        if (n < N) {
                            float2 s2 = *(const float2*)(g_S2 + (size_t)n * D + col);
                            *(float2*)(dout + (size_t)n * D + col) =
                                make_float2(v0 + s2.x, v1 + s2.y);
                        }
                    } else {
                        outh[(size_t)n * 64 + (col >> 1)] = hpack(v0, v1);
                        if (mode == 1 && n < N) {
                            ls[nf * 2]     += v0; lq[nf * 2]     += v0 * v0;
                            ls[nf * 2 + 1] += v1; lq[nf * 2 + 1] += v1 * v1;
                        }
                    }
                }
            }
        }
        if (mode == 1) {
            #pragma unroll
            for (int i = 0; i < 8; i++) {
                #pragma unroll
                for (int off = 4; off < 32; off <<= 1) {
                    ls[i] += __shfl_xor_sync(0xffffffffu, ls[i], off);
                    lq[i] += __shfl_xor_sync(0xffffffffu, lq[i], off);
                }
            }
            if (g == 0) {
                #pragma unroll
                for (int nf = 0; nf < 4; nf++) {
                    #pragma unroll
                    for (int j = 0; j < 2; j++) {
                        int col = warpN * 32 + nf * 8 + 2 * tg + j;
                        atomicAdd(&g_colsum[sidx][col], ls[nf * 2 + j]);
                        atomicAdd(&g_colsq[sidx][col],  lq[nf * 2 + j]);
                    }
                }
            }
        }
        if (s + 1 < nsub) {
            CP_WAIT();
            __syncthreads();
        }
    }
}

// ---------------- stage-2: predictor (1-term fp16) + cosine loss ----------------
__global__ __launch_bounds__(256, 2) void k_pred_s2(
    const float* __restrict__ bng, const float* __restrict__ bnb,
    const float* __restrict__ b2, const float* __restrict__ prelu_a, int N)
{
    extern __shared__ uint32_t sm[];
    float* bias_s = (float*)(sm + SM_BIAS);
    float* sred   = (float*)(sm + SM_RED);   // psq[128], dot[128], tsq[128]
    float* bnsc   = (float*)(sm + SM_BN);
    float* bnsh   = bnsc + 128;
    uint32_t sb = smem_u32(sm);

    int tag = blockIdx.y;
    int row0 = blockIdx.x * 128;
    int tid = threadIdx.x;
    int wid = tid >> 5, lane = tid & 31;
    int g = lane >> 2, tg = lane & 3;
    int warpM = wid & 1, warpN = wid >> 1;
    const uint32_t* H = tag ? g_Hy : g_Hx;
    const uint32_t* T = tag ? g_TgtY : g_TgtX;
    float slope = prelu_a[0];

    copyB(sb, tid, g_Bh[3]);                  // W2, async under BN compute
    if (tid < 128) {
        float inv = 1.f / (float)N;
        float mu  = g_colsum[tag][tid] * inv;
        float var = g_colsq[tag][tid] * inv - mu * mu;
        float istd = rsqrtf(var + 1e-5f);
        float sc = bng[tid] * istd;
        bnsc[tid] = sc;
        bnsh[tid] = bnb[tid] - mu * sc;
        bias_s[tid] = b2[tid];
        sred[tid] = 0.f; sred[128 + tid] = 0.f; sred[256 + tid] = 0.f;
    }
    __syncthreads();

    // fill A = PReLU(BN(H)) from packed-half2 H
    {
        int m = tid >> 1, half = tid & 1;
        const uint4* hrow = (const uint4*)(H + (size_t)(row0 + m) * 64 + half * 32);
        const float2* scp = (const float2*)bnsc + half * 32;
        const float2* shp = (const float2*)bnsh + half * 32;
        uint32_t* dH = sm + SM_AH + m * PA + half * 32;
        #pragma unroll
        for (int j = 0; j < 8; j++) {
            uint4 hv = hrow[j];
            uint32_t comps[4] = {hv.x, hv.y, hv.z, hv.w};
            #pragma unroll
            for (int q = 0; q < 4; q++) {
                float2 f  = hunpack(comps[q]);
                float2 sc = scp[j * 4 + q];
                float2 sh = shp[j * 4 + q];
                float a0 = fmaf(f.x, sc.x, sh.x);
                float a1 = fmaf(f.y, sc.y, sh.y);
                a0 = a0 > 0.f ? a0 : slope * a0;
                a1 = a1 > 0.f ? a1 : slope * a1;
                dH[j * 4 + q] = hpack(a0, a1);
            }
        }
    }
    CP_WAIT();
    __syncthreads();

    float c[4][4][4];
    #pragma unroll
    for (int mf = 0; mf < 4; mf++)
        #pragma unroll
        for (int nf = 0; nf < 4; nf++)
            #pragma unroll
            for (int q = 0; q < 4; q++) c[mf][nf][q] = 0.f;

    mma_pass(sb, wid, lane, c, false);   // 1-term fp16

    #pragma unroll
    for (int mf = 0; mf < 4; mf++) {
        #pragma unroll
        for (int part = 0; part < 2; part++) {
            int r = warpM * 64 + mf * 16 + g + part * 8;
            int n = row0 + r;
            float psq = 0.f, dot = 0.f, tsq = 0.f;
            #pragma unroll
            for (int nf = 0; nf < 4; nf++) {
                int col = warpN * 32 + nf * 8 + 2 * tg;
                float v0 = c[mf][nf][part * 2]     + bias_s[col];
                float v1 = c[mf][nf][part * 2 + 1] + bias_s[col + 1];
                float2 t2 = hunpack(T[(size_t)n * 64 + (col >> 1)]);
                psq = fmaf(v0, v0, fmaf(v1, v1, psq));
                dot = fmaf(v0, t2.x, fmaf(v1, t2.y, dot));
                tsq = fmaf(t2.x, t2.x, fmaf(t2.y, t2.y, tsq));
            }
            // pre-reduce across the tg quad (lanes xor 1,2 share row r) -> 1/4 atomics
            psq += __shfl_xor_sync(0xffffffffu, psq, 1);
            psq += __shfl_xor_sync(0xffffffffu, psq, 2);
            dot += __shfl_xor_sync(0xffffffffu, dot, 1);
            dot += __shfl_xor_sync(0xffffffffu, dot, 2);
            tsq += __shfl_xor_sync(0xffffffffu, tsq, 1);
            tsq += __shfl_xor_sync(0xffffffffu, tsq, 2);
            if (tg == 0) {
                atomicAdd(&sred[r], psq);
                atomicAdd(&sred[128 + r], dot);
                atomicAdd(&sred[256 + r], tsq);
            }
        }
    }
    __syncthreads();

    if (tid < 128) {
        int n = row0 + tid;
        float lossv = 0.f;
        if (n < N) {
            float denom = fmaxf(sqrtf(sred[tid]), 1e-12f) *
                          fmaxf(sqrtf(sred[256 + tid]), 1e-12f);
            lossv = 2.f - 2.f * sred[128 + tid] / denom;
        }
        #pragma unroll
        for (int o = 16; o; o >>= 1) lossv += __shfl_xor_sync(0xffffffffu, lossv, o);
        if (lane == 0) atomicAdd(&g_lossSum, (double)lossv);
    }
}

__global__ void k_final(float* __restrict__ dout, int N) {
    dout[(size_t)N * D] = (float)(g_lossSum / (double)N);
}

// ---------------- launch ----------------
extern "C" void kernel_launch(void* const* d_in, const int* in_sizes, int n_in,
                              void* d_out, int out_size) {
    const float* x    = (const float*)d_in[0];
    const float* perb = (const float*)d_in[1];
    const int*   erow = (const int*)d_in[2];
    const int*   ecol = (const int*)d_in[3];
    const float* ew   = (const float*)d_in[4];
    const float* Won  = (const float*)d_in[5];
    const float* bon  = (const float*)d_in[6];
    const float* Wtg  = (const float*)d_in[7];
    const float* btg  = (const float*)d_in[8];
    const float* W1   = (const float*)d_in[9];
    const float* b1   = (const float*)d_in[10];
    const float* bng  = (const float*)d_in[11];
    const float* bnb  = (const float*)d_in[12];
    const float* pa   = (const float*)d_in[13];
    const float* W2   = (const float*)d_in[14];
    const float* b2   = (const float*)d_in[15];
    float* out = (float*)d_out;

    int N = in_sizes[0] / D;
    int E = in_sizes[2];
    if (N > NPAD) N = NPAD;
    if (E > EMAX) E = EMAX;

    cudaFuncSetAttribute(k_gemm_s1, cudaFuncAttributeMaxDynamicSharedMemorySize, DYN_SMEM);
    cudaFuncSetAttribute(k_pred_s2, cudaFuncAttributeMaxDynamicSharedMemorySize, DYN_SMEM);

    const int PREPB = NPAD * 32 / 256;       // 6256
    int EB = (E + 255) / 256;

    k_prep_count<<<PREPB + EB, 256>>>(x, perb, erow, N, E, PREPB);
    k_scan<<<1, 1024>>>();
    k_scatter_combine<<<EB + D + 1, 256>>>(erow, ecol, ew, Won, bon, W1, b1, E, EB);
    k_agg_wprep<<<16 + NPAD / 8, 256>>>(x, Wtg, Won, W2);
    dim3 g1(NBLK, 2);
    k_gemm_s1<<<g1, 256, DYN_SMEM>>>(bon, btg, out, N);
    dim3 g2(NBLK, 2);
    k_pred_s2<<<g2, 256, DYN_SMEM>>>(bng, bnb, b2, pa, N);
    k_final<<<1, 1>>>(out, N);
}